// round 15
// baseline (speedup 1.0000x reference)
#include <cuda_runtime.h>
#include <cuda_bf16.h>
#include <math.h>

// Problem constants
#define HID    1024
#define VOCAB  32000
#define BATCH  8
#define SEQ    512
#define INDIM  768
#define MROWS  (BATCH*SEQ)      // 4096
#define GATES  (3*HID)          // 3072
#define KW     (HID/2)          // 512 b32 words per bf16 row

// ---------------- scratch (no allocation allowed -> device globals) -----------
__device__ float g_h0init[2*BATCH*HID];
__device__ float g_hA[BATCH*HID];
__device__ float g_hB[BATCH*HID];
__device__ float g_xg[(size_t)MROWS*GATES];
// bf16 hi/lo operand buffers
__device__ __nv_bfloat16 g_eh[(size_t)MROWS*HID];   // gathered embedding hi
__device__ __nv_bfloat16 g_el[(size_t)MROWS*HID];
__device__ __nv_bfloat16 g_y0h[(size_t)MROWS*HID];  // layer0 output
__device__ __nv_bfloat16 g_y0l[(size_t)MROWS*HID];
__device__ __nv_bfloat16 g_y1h[(size_t)MROWS*HID];  // layer1 output
__device__ __nv_bfloat16 g_y1l[(size_t)MROWS*HID];
__device__ __nv_bfloat16 g_wihh[(size_t)2*GATES*HID];
__device__ __nv_bfloat16 g_wihl[(size_t)2*GATES*HID];
__device__ __nv_bfloat16 g_fcwh[(size_t)VOCAB*HID];
__device__ __nv_bfloat16 g_fcwl[(size_t)VOCAB*HID];
__device__ unsigned int          g_barcnt = 0;
__device__ volatile unsigned int g_bargen = 0;

// ---------------- helpers -------------------------------------------------------
__device__ __forceinline__ unsigned pack_bf2(float a, float b)
{
    __nv_bfloat162 t = __floats2bfloat162_rn(a, b);
    return *reinterpret_cast<unsigned*>(&t);
}

__device__ __forceinline__ void split_pair(float x, float y,
                                           unsigned& hi, unsigned& lo)
{
    hi = pack_bf2(x, y);
    __nv_bfloat162 hh = *reinterpret_cast<__nv_bfloat162*>(&hi);
    lo = pack_bf2(x - __bfloat162float(hh.x), y - __bfloat162float(hh.y));
}

__device__ __forceinline__ void mma_bf16(float* d, const unsigned* a, const unsigned* b)
{
    asm volatile(
        "mma.sync.aligned.m16n8k16.row.col.f32.bf16.bf16.f32 "
        "{%0,%1,%2,%3},{%4,%5,%6,%7},{%8,%9},{%0,%1,%2,%3};"
        : "+f"(d[0]), "+f"(d[1]), "+f"(d[2]), "+f"(d[3])
        : "r"(a[0]), "r"(a[1]), "r"(a[2]), "r"(a[3]), "r"(b[0]), "r"(b[1]));
}

__device__ __forceinline__ void ldsm_x4(unsigned* r, unsigned addr)
{
    asm volatile(
        "ldmatrix.sync.aligned.m8n8.x4.shared.b16 {%0,%1,%2,%3}, [%4];"
        : "=r"(r[0]), "=r"(r[1]), "=r"(r[2]), "=r"(r[3]) : "r"(addr));
}

__device__ __forceinline__ void ldsm_x2(unsigned* r, unsigned addr)
{
    asm volatile(
        "ldmatrix.sync.aligned.m8n8.x2.shared.b16 {%0,%1}, [%2];"
        : "=r"(r[0]), "=r"(r[1]) : "r"(addr));
}

// ---------------- h0: global context + c2h projection --------------------------
__global__ void h0_kernel(const float* __restrict__ concepts,
                          const float* __restrict__ c2h_w,
                          const float* __restrict__ c2h_b)
{
    __shared__ float ctx[INDIM];
    int b = blockIdx.x, tid = threadIdx.x;
    for (int d = tid; d < INDIM; d += blockDim.x) {
        float s = 0.f;
        #pragma unroll
        for (int n = 0; n < 16; n++) s += concepts[(b*16 + n)*INDIM + d];
        ctx[d] = s * (1.0f/16.0f);
    }
    __syncthreads();
    for (int k = tid; k < 2*HID; k += blockDim.x) {
        const float* w = c2h_w + (size_t)k*INDIM;
        float acc = 0.f;
        #pragma unroll 4
        for (int d = 0; d < INDIM; d += 4) {
            acc += ctx[d+0]*w[d+0] + ctx[d+1]*w[d+1]
                 + ctx[d+2]*w[d+2] + ctx[d+3]*w[d+3];
        }
        acc += c2h_b[k];
        int l = k >> 10, j = k & (HID-1);
        g_h0init[(l*BATCH + b)*HID + j] = acc;
    }
}

// ---------------- converters ----------------------------------------------------
__global__ void conv_split(const float* __restrict__ in,
                           __nv_bfloat16* __restrict__ hi,
                           __nv_bfloat16* __restrict__ lo, int n4)
{
    int i = blockIdx.x*blockDim.x + threadIdx.x;
    if (i < n4) {
        float4 v = reinterpret_cast<const float4*>(in)[i];
        unsigned h0, l0, h1, l1;
        split_pair(v.x, v.y, h0, l0);
        split_pair(v.z, v.w, h1, l1);
        reinterpret_cast<uint2*>(hi)[i] = make_uint2(h0, h1);
        reinterpret_cast<uint2*>(lo)[i] = make_uint2(l0, l1);
    }
}

__global__ void conv_gather(const float* __restrict__ emb,
                            const int* __restrict__ seq,
                            __nv_bfloat16* __restrict__ hi,
                            __nv_bfloat16* __restrict__ lo)
{
    int m   = blockIdx.x;                 // 0..4095
    int tid = threadIdx.x;                // 256 threads, 1 float4 each
    const float4* src = reinterpret_cast<const float4*>(
        emb + (size_t)seq[m]*HID);
    float4 v = src[tid];
    unsigned h0, l0, h1, l1;
    split_pair(v.x, v.y, h0, l0);
    split_pair(v.z, v.w, h1, l1);
    reinterpret_cast<uint2*>(hi + (size_t)m*HID)[tid] = make_uint2(h0, h1);
    reinterpret_cast<uint2*>(lo + (size_t)m*HID)[tid] = make_uint2(l0, l1);
}

// ---------------- bf16x3 GEMM on pre-split operands -----------------------------
// C[M,N] = A[M,K] * B[N,K]^T + bias[N]; A,B given as bf16 hi/lo pairs.
// Tile 128(M)x64(N), BK=32 elems, 256 thr (8 warps, 4m x 2n), mma.m16n8k16,
// ldmatrix fragment loads. No conversions in the hot loop.
#define GLDW  20
#define GTA   (128*GLDW)
#define GTB   (64*GLDW)
#define GBUF  (2*GTA + 2*GTB)
#define GSMEM (2*GBUF*4)

__global__ void __launch_bounds__(256, 2)
gemm_pre(const unsigned* __restrict__ Ahg, const unsigned* __restrict__ Alg,
         const unsigned* __restrict__ Bhg, const unsigned* __restrict__ Blg,
         const float* __restrict__ bias, float* __restrict__ C,
         int M, int N)
{
    extern __shared__ unsigned sm[];
    const unsigned smb = (unsigned)__cvta_generic_to_shared(sm);
    const int tid = threadIdx.x;
    const int l   = tid & 31;
    const int wid = tid >> 5;
    const int wm  = (wid & 3) * 32;
    const int wn  = (wid >> 2) * 32;
    const int bm  = blockIdx.x * 128;
    const int bn  = blockIdx.y * 64;
    const int g   = l >> 2;
    const int t   = l & 3;
    const int lr  = l & 7;
    const int qA  = (l >> 3) & 1;
    const int qW  = (l >> 4);

    // loaders: A 512 uint4 (2/thread), B 256 uint4 (1/thread)
    int aploc[2], bploc;
    const unsigned* aph[2];
    const unsigned* apl[2];
    #pragma unroll
    for (int u = 0; u < 2; u++) {
        int f    = tid + u*256;
        int row  = f >> 2;
        int wc   = (f & 3) << 2;
        aploc[u] = row*GLDW + wc;
        aph[u]   = Ahg + (size_t)(bm + row)*KW + wc;
        apl[u]   = Alg + (size_t)(bm + row)*KW + wc;
    }
    {
        int row = tid >> 2;
        int wc  = (tid & 3) << 2;
        bploc   = row*GLDW + wc;
    }
    const unsigned* bph = Bhg + (size_t)(bn + (tid >> 2))*KW + ((tid & 3) << 2);
    const unsigned* bpl = Blg + (size_t)(bn + (tid >> 2))*KW + ((tid & 3) << 2);

    float acc[2][4][4];
    #pragma unroll
    for (int i = 0; i < 2; i++)
        #pragma unroll
        for (int jj = 0; jj < 4; jj++)
            #pragma unroll
            for (int r = 0; r < 4; r++) acc[i][jj][r] = 0.f;

    uint4 vah[2], val[2], vbh, vbl;
    auto gload = [&](int kt) {
        #pragma unroll
        for (int u = 0; u < 2; u++) {
            vah[u] = *reinterpret_cast<const uint4*>(aph[u] + kt*16);
            val[u] = *reinterpret_cast<const uint4*>(apl[u] + kt*16);
        }
        vbh = *reinterpret_cast<const uint4*>(bph + kt*16);
        vbl = *reinterpret_cast<const uint4*>(bpl + kt*16);
    };
    auto sstore = [&](int buf) {
        unsigned* Ah = sm + buf*GBUF;
        unsigned* Al = Ah + GTA;
        unsigned* Bh = Al + GTA;
        unsigned* Bl = Bh + GTB;
        #pragma unroll
        for (int u = 0; u < 2; u++) {
            *reinterpret_cast<uint4*>(&Ah[aploc[u]]) = vah[u];
            *reinterpret_cast<uint4*>(&Al[aploc[u]]) = val[u];
        }
        *reinterpret_cast<uint4*>(&Bh[bploc]) = vbh;
        *reinterpret_cast<uint4*>(&Bl[bploc]) = vbl;
    };

    const int nk = HID / 32;   // 32 k-tiles
    gload(0); sstore(0); __syncthreads();

    for (int kt = 0; kt < nk; kt++) {
        int cur = kt & 1;
        if (kt + 1 < nk) gload(kt + 1);

        const unsigned AhB = smb + (cur*GBUF)*4u;
        const unsigned AlB = AhB + GTA*4u;
        const unsigned BhB = AlB + GTA*4u;
        const unsigned BlB = BhB + GTB*4u;

        #pragma unroll
        for (int kh = 0; kh < 2; kh++) {
            const int bp = kh * 8;
            unsigned ah[2][4], al[2][4], bh[4][2], bl[4][2];
            #pragma unroll
            for (int mf = 0; mf < 2; mf++) {
                unsigned aoff = (unsigned)((wm + mf*16 + qA*8 + lr)*GLDW
                                           + bp + (qW << 2)) * 4u;
                ldsm_x4(ah[mf], AhB + aoff);
                ldsm_x4(al[mf], AlB + aoff);
            }
            #pragma unroll
            for (int p = 0; p < 2; p++) {
                unsigned boff = (unsigned)((wn + (p*2 + qW)*8 + lr)*GLDW
                                           + bp + (((l >> 3) & 1) << 2)) * 4u;
                unsigned tmp[4];
                ldsm_x4(tmp, BhB + boff);
                bh[2*p][0] = tmp[0]; bh[2*p][1] = tmp[1];
                bh[2*p+1][0] = tmp[2]; bh[2*p+1][1] = tmp[3];
                ldsm_x4(tmp, BlB + boff);
                bl[2*p][0] = tmp[0]; bl[2*p][1] = tmp[1];
                bl[2*p+1][0] = tmp[2]; bl[2*p+1][1] = tmp[3];
            }
            #pragma unroll
            for (int mf = 0; mf < 2; mf++)
                #pragma unroll
                for (int nf = 0; nf < 4; nf++) {
                    mma_bf16(acc[mf][nf], ah[mf], bh[nf]);
                    mma_bf16(acc[mf][nf], ah[mf], bl[nf]);
                    mma_bf16(acc[mf][nf], al[mf], bh[nf]);
                }
        }
        if (kt + 1 < nk) sstore(cur ^ 1);
        __syncthreads();
    }

    #pragma unroll
    for (int mf = 0; mf < 2; mf++) {
        int row = bm + wm + mf*16 + g;
        #pragma unroll
        for (int nf = 0; nf < 4; nf++) {
            int col = bn + wn + nf*8 + (t << 1);
            float b0 = bias[col], b1 = bias[col+1];
            float2 v0 = make_float2(acc[mf][nf][0] + b0, acc[mf][nf][1] + b1);
            float2 v1 = make_float2(acc[mf][nf][2] + b0, acc[mf][nf][3] + b1);
            *reinterpret_cast<float2*>(C + (size_t)row*N + col)     = v0;
            *reinterpret_cast<float2*>(C + (size_t)(row+8)*N + col) = v1;
        }
    }
}

// ---------------- tensor-core GRU layer (R13 core; bf16 y outputs) --------------
#define BROW 516
#define OFF_BL 12384
#define OFF_AH 24768
#define OFF_AL 28896
#define OFF_RED 33024
#define GRU_SMEM ((OFF_RED + 1536) * 4)

__device__ __forceinline__ void grid_sync()
{
    __threadfence();
    __syncthreads();
    if (threadIdx.x == 0) {
        unsigned int gen = g_bargen;
        if (atomicAdd(&g_barcnt, 1) == gridDim.x - 1) {
            g_barcnt = 0;
            __threadfence();
            g_bargen = gen + 1;
        } else {
            while (g_bargen == gen) { __nanosleep(64); }
        }
    }
    __syncthreads();
}

__global__ void __launch_bounds__(256, 1)
gru_tc(const float* __restrict__ xg,
       const float* __restrict__ whh,
       const float* __restrict__ bhh,
       const float* __restrict__ h0i,
       __nv_bfloat16* __restrict__ yh,
       __nv_bfloat16* __restrict__ yl,
       float* hA, float* hB)
{
    extern __shared__ unsigned smw[];
    unsigned* Bh  = smw;
    unsigned* Bl  = smw + OFF_BL;
    unsigned* Ah  = smw + OFF_AH;
    unsigned* Al  = smw + OFF_AL;
    float*    red = reinterpret_cast<float*>(smw + OFF_RED);
    const unsigned smb = (unsigned)__cvta_generic_to_shared(smw);

    const int tid = threadIdx.x;
    const int w   = tid >> 5;
    const int l   = tid & 31;
    const int g   = l >> 2;
    const int t   = l & 3;
    const int i16 = l & 15;

    #pragma unroll 4
    for (int it = 0; it < 48; it++) {
        int wi   = tid + it*256;
        int r24  = wi >> 9;
        int word = wi & 511;
        int grow = (r24 >> 3)*HID + blockIdx.x*8 + (r24 & 7);
        float2 v = *reinterpret_cast<const float2*>(whh + (size_t)grow*HID + word*2);
        unsigned hi, lo;
        split_pair(v.x, v.y, hi, lo);
        Bh[r24*BROW + word] = hi;
        Bl[r24*BROW + word] = lo;
    }
    __syncthreads();

    const int gb = tid & 7, gj = tid >> 3;
    const int jg = blockIdx.x*8 + gj;
    float br = 0.f, bz = 0.f, bn_ = 0.f, pxr = 0.f, pxz = 0.f, pxn = 0.f;
    if (tid < 64) {
        br  = bhh[jg];
        bz  = bhh[HID + jg];
        bn_ = bhh[2*HID + jg];
        size_t row = ((size_t)gb*SEQ + 0) * GATES;
        pxr = __ldg(xg + row + jg);
        pxz = __ldg(xg + row + HID + jg);
        pxn = __ldg(xg + row + 2*HID + jg);
    }

    for (int s = 0; s < SEQ; s++) {
        const float* hsrc = (s == 0) ? h0i : ((s & 1) ? hA : hB);
        float*       hdst = (s & 1) ? hB : hA;

        float hp = 0.f;
        if (tid < 64) hp = __ldcg(hsrc + gb*HID + jg);
        {
            const float4* h4 = reinterpret_cast<const float4*>(hsrc);
            #pragma unroll
            for (int it = 0; it < 8; it++) {
                int i = tid + it*256;
                float4 v = __ldcg(h4 + i);
                int row  = i >> 8;
                int word = (i & 255) << 1;
                unsigned h0w, l0w, h1w, l1w;
                split_pair(v.x, v.y, h0w, l0w);
                split_pair(v.z, v.w, h1w, l1w);
                Ah[row*BROW + word]     = h0w;
                Ah[row*BROW + word + 1] = h1w;
                Al[row*BROW + word]     = l0w;
                Al[row*BROW + word + 1] = l1w;
            }
        }
        __syncthreads();

        float acc[3][4];
        #pragma unroll
        for (int p = 0; p < 3; p++)
            #pragma unroll
            for (int r = 0; r < 4; r++) acc[p][r] = 0.f;

        #pragma unroll 2
        for (int i = 0; i < 8; i++) {
            const int c  = w*8 + i;
            const int aw = c*8 + t;
            unsigned afh[4], afl[4];
            afh[0] = Ah[g*BROW + aw]; afh[1] = 0u;
            afh[2] = Ah[g*BROW + aw + 4]; afh[3] = 0u;
            afl[0] = Al[g*BROW + aw]; afl[1] = 0u;
            afl[2] = Al[g*BROW + aw + 4]; afl[3] = 0u;
            #pragma unroll
            for (int p = 0; p < 3; p++) {
                unsigned ro = (unsigned)((p*8 + (i16 & 7))*BROW + c*8 + ((i16 >> 3) << 2));
                unsigned bfh[2], bfl[2];
                ldsm_x2(bfh, smb + ro*4u);
                ldsm_x2(bfl, smb + (OFF_BL + ro)*4u);
                mma_bf16(acc[p], afh, bfh);
                mma_bf16(acc[p], afh, bfl);
                mma_bf16(acc[p], afl, bfh);
            }
        }

        #pragma unroll
        for (int p = 0; p < 3; p++) {
            red[w*192 + (p*8 + 2*t)*8 + g]     = acc[p][0];
            red[w*192 + (p*8 + 2*t + 1)*8 + g] = acc[p][1];
        }
        __syncthreads();

        if (tid < 64) {
            float R = 0.f, Z = 0.f, Nn = 0.f;
            #pragma unroll
            for (int ww = 0; ww < 8; ww++) {
                R  += red[ww*192 + gj*8 + gb];
                Z  += red[ww*192 + (8 + gj)*8 + gb];
                Nn += red[ww*192 + (16 + gj)*8 + gb];
            }
            float rg   = 1.f / (1.f + __expf(-(pxr + R + br)));
            float zg   = 1.f / (1.f + __expf(-(pxz + Z + bz)));
            float ng   = tanhf(pxn + rg * (Nn + bn_));
            float hnew = (1.f - zg) * ng + zg * hp;
            hdst[gb*HID + jg] = hnew;
            __nv_bfloat16 hb = __float2bfloat16_rn(hnew);
            size_t yi = ((size_t)gb*SEQ + s)*HID + jg;
            yh[yi] = hb;
            yl[yi] = __float2bfloat16_rn(hnew - __bfloat162float(hb));
            if (s + 1 < SEQ) {
                size_t row = ((size_t)gb*SEQ + (s + 1)) * GATES;
                pxr = __ldg(xg + row + jg);
                pxz = __ldg(xg + row + HID + jg);
                pxn = __ldg(xg + row + 2*HID + jg);
            }
        }
        if (s + 1 < SEQ) grid_sync();
    }
}

// ---------------- launcher -----------------------------------------------------
extern "C" void kernel_launch(void* const* d_in, const int* in_sizes, int n_in,
                              void* d_out, int out_size)
{
    (void)in_sizes; (void)n_in; (void)out_size;
    const float* concepts  = (const float*)d_in[0];
    const int*   seq       = (const int*)  d_in[1];
    const float* embedding = (const float*)d_in[2];
    const float* w_ih      = (const float*)d_in[3];
    const float* w_hh      = (const float*)d_in[4];
    const float* b_ih      = (const float*)d_in[5];
    const float* b_hh      = (const float*)d_in[6];
    const float* fc_w      = (const float*)d_in[7];
    const float* fc_b      = (const float*)d_in[8];
    const float* c2h_w     = (const float*)d_in[9];
    const float* c2h_b     = (const float*)d_in[10];
    float* out = (float*)d_out;

    float *xg, *h0i, *hA, *hB;
    cudaGetSymbolAddress((void**)&xg,  g_xg);
    cudaGetSymbolAddress((void**)&h0i, g_h0init);
    cudaGetSymbolAddress((void**)&hA,  g_hA);
    cudaGetSymbolAddress((void**)&hB,  g_hB);
    __nv_bfloat16 *eh, *el, *y0h, *y0l, *y1h, *y1l, *wihh, *wihl, *fcwh, *fcwl;
    cudaGetSymbolAddress((void**)&eh,   g_eh);
    cudaGetSymbolAddress((void**)&el,   g_el);
    cudaGetSymbolAddress((void**)&y0h,  g_y0h);
    cudaGetSymbolAddress((void**)&y0l,  g_y0l);
    cudaGetSymbolAddress((void**)&y1h,  g_y1h);
    cudaGetSymbolAddress((void**)&y1l,  g_y1l);
    cudaGetSymbolAddress((void**)&wihh, g_wihh);
    cudaGetSymbolAddress((void**)&wihl, g_wihl);
    cudaGetSymbolAddress((void**)&fcwh, g_fcwh);
    cudaGetSymbolAddress((void**)&fcwl, g_fcwl);

    cudaFuncSetAttribute(gemm_pre, cudaFuncAttributeMaxDynamicSharedMemorySize, GSMEM);
    cudaFuncSetAttribute(gru_tc,   cudaFuncAttributeMaxDynamicSharedMemorySize, GRU_SMEM);

    // 0) one-time operand conversions (graph-replayed, deterministic)
    h0_kernel<<<BATCH, 256>>>(concepts, c2h_w, c2h_b);
    conv_gather<<<MROWS, 256>>>(embedding, seq, eh, el);
    conv_split<<<(2*GATES*HID/4 + 255)/256, 256>>>(w_ih, wihh, wihl, 2*GATES*HID/4);
    conv_split<<<((int)((size_t)VOCAB*HID/4) + 255)/256, 256>>>(fc_w, fcwh, fcwl,
                                                                (int)((size_t)VOCAB*HID/4));

    dim3 gx(MROWS/128, GATES/64);    // (32, 48)
    dim3 gl(MROWS/128, VOCAB/64);    // (32, 500)

    // 1) layer-0 input gates
    gemm_pre<<<gx, 256, GSMEM>>>((const unsigned*)eh, (const unsigned*)el,
                                 (const unsigned*)wihh, (const unsigned*)wihl,
                                 b_ih, xg, MROWS, GATES);
    // 2) layer-0 recurrence
    gru_tc<<<128, 256, GRU_SMEM>>>(xg, w_hh, b_hh, h0i, y0h, y0l, hA, hB);
    // 3) layer-1 input gates
    gemm_pre<<<gx, 256, GSMEM>>>((const unsigned*)y0h, (const unsigned*)y0l,
                                 (const unsigned*)(wihh + (size_t)GATES*HID),
                                 (const unsigned*)(wihl + (size_t)GATES*HID),
                                 b_ih + GATES, xg, MROWS, GATES);
    // 4) layer-1 recurrence
    gru_tc<<<128, 256, GRU_SMEM>>>(xg, w_hh + (size_t)GATES*HID, b_hh + GATES,
                                   h0i + BATCH*HID, y1h, y1l, hA, hB);
    // 5) logits
    gemm_pre<<<gl, 256, GSMEM>>>((const unsigned*)y1h, (const unsigned*)y1l,
                                 (const unsigned*)fcwh, (const unsigned*)fcwl,
                                 fc_b, out, MROWS, VOCAB);
}

// round 16
// speedup vs baseline: 1.0358x; 1.0358x over previous
#include <cuda_runtime.h>
#include <cuda_bf16.h>
#include <math.h>

// Problem constants
#define HID    1024
#define VOCAB  32000
#define BATCH  8
#define SEQ    512
#define INDIM  768
#define MROWS  (BATCH*SEQ)      // 4096
#define GATES  (3*HID)          // 3072

// ---------------- scratch (no allocation allowed -> device globals) -----------
__device__ __nv_bfloat16 g_h0h[2*BATCH*HID]; // initial h (bf16 hi)
__device__ __nv_bfloat16 g_h0l[2*BATCH*HID]; // initial h (bf16 lo)
__device__ __nv_bfloat16 g_hAh[BATCH*HID];   // ping/pong h as bf16 hi/lo
__device__ __nv_bfloat16 g_hAl[BATCH*HID];
__device__ __nv_bfloat16 g_hBh[BATCH*HID];
__device__ __nv_bfloat16 g_hBl[BATCH*HID];
__device__ float g_xg[(size_t)MROWS*GATES];  // input gates (reused per layer)
__device__ float g_y0[(size_t)MROWS*HID];
__device__ float g_y1[(size_t)MROWS*HID];
__device__ unsigned int          g_barcnt = 0;
__device__ volatile unsigned int g_bargen = 0;

// ---------------- helpers -------------------------------------------------------
__device__ __forceinline__ unsigned pack_bf2(float a, float b)
{
    __nv_bfloat162 t = __floats2bfloat162_rn(a, b);
    return *reinterpret_cast<unsigned*>(&t);
}

__device__ __forceinline__ void split_pair(float x, float y,
                                           unsigned& hi, unsigned& lo)
{
    hi = pack_bf2(x, y);
    __nv_bfloat162 hh = *reinterpret_cast<__nv_bfloat162*>(&hi);
    lo = pack_bf2(x - __bfloat162float(hh.x), y - __bfloat162float(hh.y));
}

__device__ __forceinline__ void mma_bf16(float* d, const unsigned* a, const unsigned* b)
{
    asm volatile(
        "mma.sync.aligned.m16n8k16.row.col.f32.bf16.bf16.f32 "
        "{%0,%1,%2,%3},{%4,%5,%6,%7},{%8,%9},{%0,%1,%2,%3};"
        : "+f"(d[0]), "+f"(d[1]), "+f"(d[2]), "+f"(d[3])
        : "r"(a[0]), "r"(a[1]), "r"(a[2]), "r"(a[3]), "r"(b[0]), "r"(b[1]));
}

__device__ __forceinline__ void ldsm_x4(unsigned* r, unsigned addr)
{
    asm volatile(
        "ldmatrix.sync.aligned.m8n8.x4.shared.b16 {%0,%1,%2,%3}, [%4];"
        : "=r"(r[0]), "=r"(r[1]), "=r"(r[2]), "=r"(r[3]) : "r"(addr));
}

__device__ __forceinline__ void ldsm_x2(unsigned* r, unsigned addr)
{
    asm volatile(
        "ldmatrix.sync.aligned.m8n8.x2.shared.b16 {%0,%1}, [%2];"
        : "=r"(r[0]), "=r"(r[1]) : "r"(addr));
}

// ---------------- h0: global context + c2h projection (emits bf16 hi/lo) -------
__global__ void h0_kernel(const float* __restrict__ concepts,
                          const float* __restrict__ c2h_w,
                          const float* __restrict__ c2h_b)
{
    __shared__ float ctx[INDIM];
    int b = blockIdx.x, tid = threadIdx.x;
    for (int d = tid; d < INDIM; d += blockDim.x) {
        float s = 0.f;
        #pragma unroll
        for (int n = 0; n < 16; n++) s += concepts[(b*16 + n)*INDIM + d];
        ctx[d] = s * (1.0f/16.0f);
    }
    __syncthreads();
    for (int k = tid; k < 2*HID; k += blockDim.x) {
        const float* w = c2h_w + (size_t)k*INDIM;
        float acc = 0.f;
        #pragma unroll 4
        for (int d = 0; d < INDIM; d += 4) {
            acc += ctx[d+0]*w[d+0] + ctx[d+1]*w[d+1]
                 + ctx[d+2]*w[d+2] + ctx[d+3]*w[d+3];
        }
        acc += c2h_b[k];
        int l = k >> 10, j = k & (HID-1);
        size_t idx = ((size_t)l*BATCH + b)*HID + j;
        __nv_bfloat16 hb = __float2bfloat16_rn(acc);
        g_h0h[idx] = hb;
        g_h0l[idx] = __float2bfloat16_rn(acc - __bfloat162float(hb));
    }
}

// ---------------- bf16x3 tensor-core GEMM (R13, passing, fp32 inputs) ----------
#define GLDW  20
#define GTA   (128*GLDW)
#define GTB   (64*GLDW)
#define GBUF  (2*GTA + 2*GTB)
#define GSMEM (2*GBUF*4)

template<bool GATHER>
__global__ void __launch_bounds__(256, 2)
gemm_bf16x3(const float* __restrict__ A, const float* __restrict__ B,
            const float* __restrict__ bias, float* __restrict__ C,
            const int* __restrict__ gidx, int M, int N, int K)
{
    extern __shared__ unsigned sm[];
    const unsigned smb = (unsigned)__cvta_generic_to_shared(sm);
    const int tid = threadIdx.x;
    const int l   = tid & 31;
    const int wid = tid >> 5;
    const int wm  = (wid & 3) * 32;
    const int wn  = (wid >> 2) * 32;
    const int bm  = blockIdx.x * 128;
    const int bn  = blockIdx.y * 64;
    const int g   = l >> 2;
    const int t   = l & 3;
    const int lr  = l & 7;
    const int qA  = (l >> 3) & 1;
    const int qW  = (l >> 4);

    int aploc[4], bploc[2];
    const float* aptr[4];
    const float* bptr[2];
    #pragma unroll
    for (int u = 0; u < 4; u++) {
        int f    = tid + u*256;
        int row  = f >> 3;
        int kf   = (f & 7) << 2;
        aploc[u] = row*GLDW + ((f & 7) << 1);
        int ar   = GATHER ? gidx[bm + row] : (bm + row);
        aptr[u]  = A + (size_t)ar*K + kf;
    }
    #pragma unroll
    for (int u = 0; u < 2; u++) {
        int f    = tid + u*256;
        int row  = f >> 3;
        int kf   = (f & 7) << 2;
        bploc[u] = row*GLDW + ((f & 7) << 1);
        bptr[u]  = B + (size_t)(bn + row)*K + kf;
    }

    float acc[2][4][4];
    #pragma unroll
    for (int i = 0; i < 2; i++)
        #pragma unroll
        for (int jj = 0; jj < 4; jj++)
            #pragma unroll
            for (int r = 0; r < 4; r++) acc[i][jj][r] = 0.f;

    float4 va[4], vb[2];
    auto gload = [&](int kt) {
        #pragma unroll
        for (int u = 0; u < 4; u++)
            va[u] = *reinterpret_cast<const float4*>(aptr[u] + kt*32);
        #pragma unroll
        for (int u = 0; u < 2; u++)
            vb[u] = *reinterpret_cast<const float4*>(bptr[u] + kt*32);
    };
    auto sstore = [&](int buf) {
        unsigned* Ah = sm + buf*GBUF;
        unsigned* Al = Ah + GTA;
        unsigned* Bh = Al + GTA;
        unsigned* Bl = Bh + GTB;
        #pragma unroll
        for (int u = 0; u < 4; u++) {
            unsigned h0, l0, h1, l1;
            split_pair(va[u].x, va[u].y, h0, l0);
            split_pair(va[u].z, va[u].w, h1, l1);
            Ah[aploc[u]] = h0; Ah[aploc[u]+1] = h1;
            Al[aploc[u]] = l0; Al[aploc[u]+1] = l1;
        }
        #pragma unroll
        for (int u = 0; u < 2; u++) {
            unsigned h0, l0, h1, l1;
            split_pair(vb[u].x, vb[u].y, h0, l0);
            split_pair(vb[u].z, vb[u].w, h1, l1);
            Bh[bploc[u]] = h0; Bh[bploc[u]+1] = h1;
            Bl[bploc[u]] = l0; Bl[bploc[u]+1] = l1;
        }
    };

    const int nk = K / 32;
    gload(0); sstore(0); __syncthreads();

    for (int kt = 0; kt < nk; kt++) {
        int cur = kt & 1;
        if (kt + 1 < nk) gload(kt + 1);

        const unsigned AhB = smb + (cur*GBUF)*4u;
        const unsigned AlB = AhB + GTA*4u;
        const unsigned BhB = AlB + GTA*4u;
        const unsigned BlB = BhB + GTB*4u;

        #pragma unroll
        for (int kh = 0; kh < 2; kh++) {
            const int bp = kh * 8;
            unsigned ah[2][4], al[2][4], bh[4][2], bl[4][2];
            #pragma unroll
            for (int mf = 0; mf < 2; mf++) {
                unsigned aoff = (unsigned)((wm + mf*16 + qA*8 + lr)*GLDW
                                           + bp + (qW << 2)) * 4u;
                ldsm_x4(ah[mf], AhB + aoff);
                ldsm_x4(al[mf], AlB + aoff);
            }
            #pragma unroll
            for (int p = 0; p < 2; p++) {
                unsigned boff = (unsigned)((wn + (p*2 + qW)*8 + lr)*GLDW
                                           + bp + (((l >> 3) & 1) << 2)) * 4u;
                unsigned tmp[4];
                ldsm_x4(tmp, BhB + boff);
                bh[2*p][0] = tmp[0]; bh[2*p][1] = tmp[1];
                bh[2*p+1][0] = tmp[2]; bh[2*p+1][1] = tmp[3];
                ldsm_x4(tmp, BlB + boff);
                bl[2*p][0] = tmp[0]; bl[2*p][1] = tmp[1];
                bl[2*p+1][0] = tmp[2]; bl[2*p+1][1] = tmp[3];
            }
            #pragma unroll
            for (int mf = 0; mf < 2; mf++)
                #pragma unroll
                for (int nf = 0; nf < 4; nf++) {
                    mma_bf16(acc[mf][nf], ah[mf], bh[nf]);
                    mma_bf16(acc[mf][nf], ah[mf], bl[nf]);
                    mma_bf16(acc[mf][nf], al[mf], bh[nf]);
                }
        }
        if (kt + 1 < nk) sstore(cur ^ 1);
        __syncthreads();
    }

    #pragma unroll
    for (int mf = 0; mf < 2; mf++) {
        int row = bm + wm + mf*16 + g;
        #pragma unroll
        for (int nf = 0; nf < 4; nf++) {
            int col = bn + wn + nf*8 + (t << 1);
            float b0 = bias[col], b1 = bias[col+1];
            float2 v0 = make_float2(acc[mf][nf][0] + b0, acc[mf][nf][1] + b1);
            float2 v1 = make_float2(acc[mf][nf][2] + b0, acc[mf][nf][3] + b1);
            *reinterpret_cast<float2*>(C + (size_t)row*N + col)     = v0;
            *reinterpret_cast<float2*>(C + (size_t)(row+8)*N + col) = v1;
        }
    }
}

// ---------------- tensor-core GRU layer (h carried as bf16 hi/lo) ---------------
#define BROW 516
#define OFF_BL 12384
#define OFF_AH 24768
#define OFF_AL 28896
#define OFF_RED 33024
#define GRU_SMEM ((OFF_RED + 1536) * 4)

__device__ __forceinline__ void grid_sync()
{
    __threadfence();
    __syncthreads();
    if (threadIdx.x == 0) {
        unsigned int gen = g_bargen;
        if (atomicAdd(&g_barcnt, 1) == gridDim.x - 1) {
            g_barcnt = 0;
            __threadfence();
            g_bargen = gen + 1;
        } else {
            while (g_bargen == gen) { __nanosleep(64); }
        }
    }
    __syncthreads();
}

__global__ void __launch_bounds__(256, 1)
gru_tc(const float* __restrict__ xg,
       const float* __restrict__ whh,
       const float* __restrict__ bhh,
       const __nv_bfloat16* __restrict__ h0h,
       const __nv_bfloat16* __restrict__ h0l,
       float* __restrict__ y,
       __nv_bfloat16* hAh, __nv_bfloat16* hAl,
       __nv_bfloat16* hBh, __nv_bfloat16* hBl)
{
    extern __shared__ unsigned smw[];
    unsigned* Bh  = smw;
    unsigned* Bl  = smw + OFF_BL;
    unsigned* Ah  = smw + OFF_AH;
    unsigned* Al  = smw + OFF_AL;
    float*    red = reinterpret_cast<float*>(smw + OFF_RED);
    const unsigned smb = (unsigned)__cvta_generic_to_shared(smw);

    const int tid = threadIdx.x;
    const int w   = tid >> 5;
    const int l   = tid & 31;
    const int g   = l >> 2;
    const int t   = l & 3;
    const int i16 = l & 15;

    // prologue: whh block rows -> bf16 hi/lo smem [24][BROW]
    #pragma unroll 4
    for (int it = 0; it < 48; it++) {
        int wi   = tid + it*256;
        int r24  = wi >> 9;
        int word = wi & 511;
        int grow = (r24 >> 3)*HID + blockIdx.x*8 + (r24 & 7);
        float2 v = *reinterpret_cast<const float2*>(whh + (size_t)grow*HID + word*2);
        unsigned hi, lo;
        split_pair(v.x, v.y, hi, lo);
        Bh[r24*BROW + word] = hi;
        Bl[r24*BROW + word] = lo;
    }
    __syncthreads();

    const int gb = tid & 7, gj = tid >> 3;   // gate threads: tid<64
    const int jg = blockIdx.x*8 + gj;
    float br = 0.f, bz = 0.f, bn_ = 0.f, pxr = 0.f, pxz = 0.f, pxn = 0.f;
    if (tid < 64) {
        br  = bhh[jg];
        bz  = bhh[HID + jg];
        bn_ = bhh[2*HID + jg];
        size_t row = ((size_t)gb*SEQ + 0) * GATES;
        pxr = __ldg(xg + row + jg);
        pxz = __ldg(xg + row + HID + jg);
        pxn = __ldg(xg + row + 2*HID + jg);
    }

    for (int s = 0; s < SEQ; s++) {
        const __nv_bfloat16* sh = (s == 0) ? h0h : ((s & 1) ? hAh : hBh);
        const __nv_bfloat16* sl = (s == 0) ? h0l : ((s & 1) ? hAl : hBl);
        __nv_bfloat16* dh = (s & 1) ? hBh : hAh;
        __nv_bfloat16* dl = (s & 1) ? hBl : hAl;

        // stage h hi/lo -> A tiles (no conversion; 1024 uint4 per matrix)
        {
            const uint4* ph = reinterpret_cast<const uint4*>(sh);
            const uint4* pl = reinterpret_cast<const uint4*>(sl);
            #pragma unroll
            for (int it = 0; it < 4; it++) {
                int i    = tid + it*256;         // 0..1023
                int row  = i >> 7;               // 0..7
                int word = (i & 127) << 2;       // 0..508
                *reinterpret_cast<uint4*>(&Ah[row*BROW + word]) = __ldcg(ph + i);
                *reinterpret_cast<uint4*>(&Al[row*BROW + word]) = __ldcg(pl + i);
            }
        }
        __syncthreads();

        // mma over this warp's 8 ktiles; even/odd ktile accumulator split for ILP
        float acc[2][3][4];
        #pragma unroll
        for (int q = 0; q < 2; q++)
            #pragma unroll
            for (int p = 0; p < 3; p++)
                #pragma unroll
                for (int r = 0; r < 4; r++) acc[q][p][r] = 0.f;

        #pragma unroll 2
        for (int i = 0; i < 8; i++) {
            const int q  = i & 1;
            const int c  = w*8 + i;
            const int aw = c*8 + t;
            unsigned afh[4], afl[4];
            afh[0] = Ah[g*BROW + aw]; afh[1] = 0u;
            afh[2] = Ah[g*BROW + aw + 4]; afh[3] = 0u;
            afl[0] = Al[g*BROW + aw]; afl[1] = 0u;
            afl[2] = Al[g*BROW + aw + 4]; afl[3] = 0u;
            #pragma unroll
            for (int p = 0; p < 3; p++) {
                unsigned ro = (unsigned)((p*8 + (i16 & 7))*BROW + c*8 + ((i16 >> 3) << 2));
                unsigned bfh[2], bfl[2];
                ldsm_x2(bfh, smb + ro*4u);
                ldsm_x2(bfl, smb + (OFF_BL + ro)*4u);
                mma_bf16(acc[q][p], afh, bfh);
                mma_bf16(acc[q][p], afh, bfl);
                mma_bf16(acc[q][p], afl, bfh);
            }
        }

        #pragma unroll
        for (int p = 0; p < 3; p++) {
            red[w*192 + (p*8 + 2*t)*8 + g]     = acc[0][p][0] + acc[1][p][0];
            red[w*192 + (p*8 + 2*t + 1)*8 + g] = acc[0][p][1] + acc[1][p][1];
        }
        __syncthreads();

        if (tid < 64) {
            float R = 0.f, Z = 0.f, Nn = 0.f;
            #pragma unroll
            for (int ww = 0; ww < 8; ww++) {
                R  += red[ww*192 + gj*8 + gb];
                Z  += red[ww*192 + (8 + gj)*8 + gb];
                Nn += red[ww*192 + (16 + gj)*8 + gb];
            }
            // exact-enough hprev from staged hi/lo (still resident in smem)
            float hp =
                __bfloat162float(reinterpret_cast<const __nv_bfloat16*>(Ah + gb*BROW)[jg]) +
                __bfloat162float(reinterpret_cast<const __nv_bfloat16*>(Al + gb*BROW)[jg]);
            float rg   = 1.f / (1.f + __expf(-(pxr + R + br)));
            float zg   = 1.f / (1.f + __expf(-(pxz + Z + bz)));
            float ng   = tanhf(pxn + rg * (Nn + bn_));
            float hnew = (1.f - zg) * ng + zg * hp;
            __nv_bfloat16 hb = __float2bfloat16_rn(hnew);
            dh[gb*HID + jg] = hb;
            dl[gb*HID + jg] = __float2bfloat16_rn(hnew - __bfloat162float(hb));
            y[((size_t)gb*SEQ + s)*HID + jg] = hnew;
            if (s + 1 < SEQ) {
                size_t row = ((size_t)gb*SEQ + (s + 1)) * GATES;
                pxr = __ldg(xg + row + jg);
                pxz = __ldg(xg + row + HID + jg);
                pxn = __ldg(xg + row + 2*HID + jg);
            }
        }
        if (s + 1 < SEQ) grid_sync();
    }
}

// ---------------- launcher -----------------------------------------------------
extern "C" void kernel_launch(void* const* d_in, const int* in_sizes, int n_in,
                              void* d_out, int out_size)
{
    (void)in_sizes; (void)n_in; (void)out_size;
    const float* concepts  = (const float*)d_in[0];
    const int*   seq       = (const int*)  d_in[1];
    const float* embedding = (const float*)d_in[2];
    const float* w_ih      = (const float*)d_in[3];
    const float* w_hh      = (const float*)d_in[4];
    const float* b_ih      = (const float*)d_in[5];
    const float* b_hh      = (const float*)d_in[6];
    const float* fc_w      = (const float*)d_in[7];
    const float* fc_b      = (const float*)d_in[8];
    const float* c2h_w     = (const float*)d_in[9];
    const float* c2h_b     = (const float*)d_in[10];
    float* out = (float*)d_out;

    float *xg, *y0, *y1;
    cudaGetSymbolAddress((void**)&xg, g_xg);
    cudaGetSymbolAddress((void**)&y0, g_y0);
    cudaGetSymbolAddress((void**)&y1, g_y1);
    __nv_bfloat16 *h0h, *h0l, *hAh, *hAl, *hBh, *hBl;
    cudaGetSymbolAddress((void**)&h0h, g_h0h);
    cudaGetSymbolAddress((void**)&h0l, g_h0l);
    cudaGetSymbolAddress((void**)&hAh, g_hAh);
    cudaGetSymbolAddress((void**)&hAl, g_hAl);
    cudaGetSymbolAddress((void**)&hBh, g_hBh);
    cudaGetSymbolAddress((void**)&hBl, g_hBl);

    cudaFuncSetAttribute(gemm_bf16x3<true>,  cudaFuncAttributeMaxDynamicSharedMemorySize, GSMEM);
    cudaFuncSetAttribute(gemm_bf16x3<false>, cudaFuncAttributeMaxDynamicSharedMemorySize, GSMEM);
    cudaFuncSetAttribute(gru_tc, cudaFuncAttributeMaxDynamicSharedMemorySize, GRU_SMEM);

    // 1) initial hidden states (bf16 hi/lo)
    h0_kernel<<<BATCH, 256>>>(concepts, c2h_w, c2h_b);

    dim3 gx(MROWS/128, GATES/64);    // (32, 48)
    dim3 gl(MROWS/128, VOCAB/64);    // (32, 500)

    // 2) layer-0 input gates (embedding gather fused)
    gemm_bf16x3<true><<<gx, 256, GSMEM>>>(embedding, w_ih, b_ih, xg, seq,
                                          MROWS, GATES, HID);
    // 3) layer-0 recurrence
    gru_tc<<<128, 256, GRU_SMEM>>>(xg, w_hh, b_hh, h0h, h0l, y0,
                                   hAh, hAl, hBh, hBl);
    // 4) layer-1 input gates
    gemm_bf16x3<false><<<gx, 256, GSMEM>>>(y0, w_ih + (size_t)GATES*HID,
                                           b_ih + GATES, xg, nullptr,
                                           MROWS, GATES, HID);
    // 5) layer-1 recurrence
    gru_tc<<<128, 256, GRU_SMEM>>>(xg, w_hh + (size_t)GATES*HID, b_hh + GATES,
                                   h0h + BATCH*HID, h0l + BATCH*HID, y1,
                                   hAh, hAl, hBh, hBl);
    // 6) logits
    gemm_bf16x3<false><<<gl, 256, GSMEM>>>(y1, fc_w, fc_b, out, nullptr,
                                           MROWS, VOCAB, HID);
}